// round 2
// baseline (speedup 1.0000x reference)
#include <cuda_runtime.h>
#include <cstdint>
#include <cstddef>

// ----------------------------------------------------------------------------
// LinearAttentionBlock — Round 1 (SIMT fp32 GEMM pipeline, double-buffered smem)
//
//   Q = phi(x@Wq + bq); K = phi(x@Wk + bk); V = x@Wv + bv        (phi = elu+1)
//   S = tril(Q K^T)   (per batch)
//   den = rowsum(S) + EPS
//   A = (S @ V) / den
//   out = A @ Wo + bo
// ----------------------------------------------------------------------------

#define BM 128
#define BN 128
#define BK 16
#define TM 8
#define TN 8

static constexpr int BATCH = 4;
static constexpr int SEQ   = 2048;
static constexpr int DMODEL = 1024;
static constexpr int DINNER = 2048;
static constexpr float EPSV = 1e-6f;

// Static scratch (no allocations allowed). ~320 MB total.
__device__ float g_Q [BATCH * SEQ * DINNER];
__device__ float g_K [BATCH * SEQ * DINNER];
__device__ float g_V [BATCH * SEQ * DINNER];
__device__ float g_Sc[BATCH * SEQ * SEQ];
__device__ float g_At[BATCH * SEQ * DINNER];
__device__ float g_den[BATCH * SEQ];

struct Smem {
    float As[2][BK][BM];
    float Bs[2][BK][BN];
};

// Load a BMxBK tile of a row-major matrix (leading dim ld) at (row0, k0),
// stored TRANSPOSED into s[BK][BM]. 256 threads, float4 global loads.
__device__ __forceinline__ void load_tileT(float s[BK][BM],
                                           const float* __restrict__ A,
                                           int ld, int row0, int k0, int tid) {
    #pragma unroll
    for (int f = tid; f < (BM * BK) / 4; f += 256) {
        int r  = f >> 2;      // 4 float4 per row (BK=16 floats)
        int c4 = f & 3;
        float4 v = *reinterpret_cast<const float4*>(
            A + (size_t)(row0 + r) * ld + k0 + c4 * 4);
        s[c4 * 4 + 0][r] = v.x;
        s[c4 * 4 + 1][r] = v.y;
        s[c4 * 4 + 2][r] = v.z;
        s[c4 * 4 + 3][r] = v.w;
    }
}

// Load a BKxBN tile of a row-major matrix (leading dim ld) at (k0, col0)
// directly into s[BK][BN].
__device__ __forceinline__ void load_tileN(float s[BK][BN],
                                           const float* __restrict__ Bm,
                                           int ld, int k0, int col0, int tid) {
    #pragma unroll
    for (int f = tid; f < (BK * BN) / 4; f += 256) {
        int r  = f >> 5;      // 32 float4 per row (BN=128 floats)
        int c4 = f & 31;
        float4 v = *reinterpret_cast<const float4*>(
            Bm + (size_t)(k0 + r) * ld + col0 + c4 * 4);
        *reinterpret_cast<float4*>(&s[r][c4 * 4]) = v;
    }
}

// 16-deep k inner product on the 128x128 tile; 8x8 per-thread micro-tile.
__device__ __forceinline__ void mma16(const float As[BK][BM],
                                      const float Bs[BK][BN],
                                      float acc[TM][TN], int trow, int tcol) {
    #pragma unroll
    for (int k = 0; k < BK; k++) {
        float a[TM], b[TN];
        #pragma unroll
        for (int i = 0; i < TM; i++) a[i] = As[k][trow * TM + i];
        #pragma unroll
        for (int j = 0; j < TN; j++) b[j] = Bs[k][tcol * TN + j];
        #pragma unroll
        for (int i = 0; i < TM; i++)
            #pragma unroll
            for (int j = 0; j < TN; j++)
                acc[i][j] = fmaf(a[i], b[j], acc[i][j]);
    }
}

// ---------------------------------------------------------------------------
// Generic double-buffered tile loop.
// MODE_A: 0 -> load_tileT(A) ; MODE_B: 0 -> load_tileN(B), 1 -> load_tileT(B)
// ---------------------------------------------------------------------------
template <int MODE_B>
__device__ __forceinline__ void gemm_core(Smem& sm,
                                          const float* __restrict__ A, int lda, int row0,
                                          const float* __restrict__ B, int ldb, int col0,
                                          int kend, float acc[TM][TN],
                                          int tid, int trow, int tcol) {
    // prologue: stage 0
    load_tileT(sm.As[0], A, lda, row0, 0, tid);
    if (MODE_B == 0) load_tileN(sm.Bs[0], B, ldb, 0, col0, tid);
    else             load_tileT(sm.Bs[0], B, ldb, col0, 0, tid);
    __syncthreads();

    int buf = 0;
    for (int k0 = BK; k0 < kend; k0 += BK) {
        int nb = buf ^ 1;
        load_tileT(sm.As[nb], A, lda, row0, k0, tid);
        if (MODE_B == 0) load_tileN(sm.Bs[nb], B, ldb, k0, col0, tid);
        else             load_tileT(sm.Bs[nb], B, ldb, col0, k0, tid);
        mma16(sm.As[buf], sm.Bs[buf], acc, trow, tcol);
        __syncthreads();
        buf = nb;
    }
    mma16(sm.As[buf], sm.Bs[buf], acc, trow, tcol);
}

// ---------------------------------------------------------------------------
// Kernel 1 & 5: C[M,Nc] = act(A[M,Kc] @ W[Kc,Nc] + bias[Nc])
// PHI=true applies elu(x)+1 = (x>0 ? x+1 : exp(x)).
// ---------------------------------------------------------------------------
template <bool PHI>
__global__ void __launch_bounds__(256, 1)
gemm_bias_kernel(const float* __restrict__ A, const float* __restrict__ W,
                 const float* __restrict__ bias, float* __restrict__ C,
                 int M, int Nc, int Kc) {
    __shared__ Smem sm;
    int tid = threadIdx.x;
    int m0 = blockIdx.y * BM;
    int n0 = blockIdx.x * BN;
    int trow = tid >> 4, tcol = tid & 15;

    float acc[TM][TN] = {};
    gemm_core<0>(sm, A, Kc, m0, W, Nc, n0, Kc, acc, tid, trow, tcol);

    #pragma unroll
    for (int i = 0; i < TM; i++) {
        int r = m0 + trow * TM + i;
        #pragma unroll
        for (int j = 0; j < TN; j++) {
            int c = n0 + tcol * TN + j;
            float v = acc[i][j] + bias[c];
            if (PHI) v = (v > 0.f) ? (v + 1.f) : __expf(v);
            C[(size_t)r * Nc + c] = v;
        }
    }
}

// ---------------------------------------------------------------------------
// Kernel 2: scores = tril(Q K^T) per batch. NT gemm; lower-triangle blocks only.
// ---------------------------------------------------------------------------
__global__ void __launch_bounds__(256, 1)
scores_kernel() {
    int bc = blockIdx.x, br = blockIdx.y, b = blockIdx.z;
    if (bc > br) return;   // strictly-upper blocks: never written, never read

    const float* Q = g_Q + (size_t)b * SEQ * DINNER;
    const float* K = g_K + (size_t)b * SEQ * DINNER;
    float* Sc      = g_Sc + (size_t)b * SEQ * SEQ;

    __shared__ Smem sm;
    int tid = threadIdx.x;
    int n0 = br * BM;   // query rows
    int m0 = bc * BN;   // key cols
    int trow = tid >> 4, tcol = tid & 15;

    float acc[TM][TN] = {};
    gemm_core<1>(sm, Q, DINNER, n0, K, DINNER, m0, DINNER, acc, tid, trow, tcol);

    #pragma unroll
    for (int i = 0; i < TM; i++) {
        int n = n0 + trow * TM + i;
        #pragma unroll
        for (int j = 0; j < TN; j++) {
            int m = m0 + tcol * TN + j;
            Sc[(size_t)n * SEQ + m] = (m <= n) ? acc[i][j] : 0.f;
        }
    }
}

// ---------------------------------------------------------------------------
// Kernel 3: den[b,n] = sum_{m<=n} scores[b,n,m] + EPS
// One 256-thread block per row; warp-shuffle reduction.
// ---------------------------------------------------------------------------
__global__ void __launch_bounds__(256)
rowsum_kernel() {
    int idx = blockIdx.x;            // b*SEQ + n
    int b = idx / SEQ, n = idx % SEQ;
    const float* row = g_Sc + (size_t)b * SEQ * SEQ + (size_t)n * SEQ;

    float s = 0.f;
    for (int m = threadIdx.x; m <= n; m += 256) s += row[m];

    #pragma unroll
    for (int off = 16; off > 0; off >>= 1)
        s += __shfl_xor_sync(0xffffffffu, s, off);

    __shared__ float red[8];
    if ((threadIdx.x & 31) == 0) red[threadIdx.x >> 5] = s;
    __syncthreads();
    if (threadIdx.x == 0) {
        float t = 0.f;
        #pragma unroll
        for (int w = 0; w < 8; w++) t += red[w];
        g_den[idx] = t + EPSV;
    }
}

// ---------------------------------------------------------------------------
// Kernel 4: A = (scores @ V) / den, per batch. k-loop bounded at diagonal.
// ---------------------------------------------------------------------------
__global__ void __launch_bounds__(256, 1)
attn_kernel() {
    int bcn = blockIdx.x, br = blockIdx.y, b = blockIdx.z;
    const float* Sc = g_Sc + (size_t)b * SEQ * SEQ;
    const float* V  = g_V  + (size_t)b * SEQ * DINNER;
    float* At       = g_At + (size_t)b * SEQ * DINNER;

    __shared__ Smem sm;
    int tid = threadIdx.x;
    int n0 = br * BM;
    int c0 = bcn * BN;
    int kend = (br + 1) * BM;   // causal: scores are 0 beyond the diagonal block
    int trow = tid >> 4, tcol = tid & 15;

    float acc[TM][TN] = {};
    gemm_core<0>(sm, Sc, SEQ, n0, V, DINNER, c0, kend, acc, tid, trow, tcol);

    #pragma unroll
    for (int i = 0; i < TM; i++) {
        int n = n0 + trow * TM + i;
        float inv = 1.f / g_den[b * SEQ + n];   // den already includes EPS
        #pragma unroll
        for (int j = 0; j < TN; j++) {
            int c = c0 + tcol * TN + j;
            At[(size_t)n * DINNER + c] = acc[i][j] * inv;
        }
    }
}

// ---------------------------------------------------------------------------
// Host launch
// ---------------------------------------------------------------------------
extern "C" void kernel_launch(void* const* d_in, const int* in_sizes, int n_in,
                              void* d_out, int out_size) {
    const float* x  = (const float*)d_in[0];
    const float* Wq = (const float*)d_in[1];
    const float* bq = (const float*)d_in[2];
    const float* Wk = (const float*)d_in[3];
    const float* bk = (const float*)d_in[4];
    const float* Wv = (const float*)d_in[5];
    const float* bv = (const float*)d_in[6];
    const float* Wo = (const float*)d_in[7];
    const float* bo = (const float*)d_in[8];
    float* out = (float*)d_out;

    float *pQ, *pK, *pV, *pAt;
    cudaGetSymbolAddress((void**)&pQ,  g_Q);
    cudaGetSymbolAddress((void**)&pK,  g_K);
    cudaGetSymbolAddress((void**)&pV,  g_V);
    cudaGetSymbolAddress((void**)&pAt, g_At);

    const int M = BATCH * SEQ;   // 8192
    dim3 blk(256);

    // 1) projections
    dim3 gproj(DINNER / BN, M / BM);
    gemm_bias_kernel<true ><<<gproj, blk>>>(x, Wq, bq, pQ, M, DINNER, DMODEL);
    gemm_bias_kernel<true ><<<gproj, blk>>>(x, Wk, bk, pK, M, DINNER, DMODEL);
    gemm_bias_kernel<false><<<gproj, blk>>>(x, Wv, bv, pV, M, DINNER, DMODEL);

    // 2) scores = tril(Q K^T)
    dim3 gsc(SEQ / BN, SEQ / BM, BATCH);
    scores_kernel<<<gsc, blk>>>();

    // 3) denominator
    rowsum_kernel<<<BATCH * SEQ, blk>>>();

    // 4) attn = (scores @ V) / den
    dim3 gat(DINNER / BN, SEQ / BM, BATCH);
    attn_kernel<<<gat, blk>>>();

    // 5) out = attn @ Wo + bo
    dim3 gout(DMODEL / BN, M / BM);
    gemm_bias_kernel<false><<<gout, blk>>>(pAt, Wo, bo, out, M, DMODEL, DINNER);
}

// round 5
// speedup vs baseline: 3.0907x; 3.0907x over previous
#include <cuda_runtime.h>
#include <cuda_bf16.h>
#include <cstdint>
#include <cstddef>

// ============================================================================
// LinearAttentionBlock — Round 5: mma.sync (HMMA) bf16x3 split-GEMM pipeline.
// tcgen05 is unavailable: harness compiles for base sm_100 (no 'a' suffix).
//
//   Every fp32 GEMM  C = A @ B  runs on tensor cores as
//      C ≈ Ah·Bh + Ah·Bl + Al·Bh     (bf16 hi + bf16 residual, fp32 accum)
//
//   Stages:
//     x -> xh/xl ;  W* -> W*T hi/lo (transposed: B operand is [N,K] K-major)
//     Q = phi(x Wq + bq), K = phi(x Wk + bk)   [epilogue splits to hi/lo]
//     V = x Wv + bv (fp32) -> transpose-split to VT hi/lo
//     S = tril(Q K^T) per batch  [epilogue masks + splits]
//     den = rowsum(S) + eps
//     At = (S V) / den           [epilogue divides + splits]
//     out = At Wo + bo           [fp32 epilogue -> d_out]
// ============================================================================

typedef __nv_bfloat16 bf;

static constexpr int BATCH  = 4;
static constexpr int SEQ    = 2048;
static constexpr int DMODEL = 1024;
static constexpr int DINNER = 2048;
static constexpr int MTOT   = BATCH * SEQ;    // 8192

// ---------------------------------------------------------------------------
// PTX helpers
// ---------------------------------------------------------------------------
__device__ __forceinline__ uint32_t smem_to_u32(const void* p) {
    uint32_t a;
    asm("{ .reg .u64 t; cvta.to.shared.u64 t, %1; cvt.u32.u64 %0, t; }"
        : "=r"(a) : "l"(p));
    return a;
}

#define CP_ASYNC16(dst, src) \
    asm volatile("cp.async.cg.shared.global [%0], [%1], 16;" \
                 :: "r"(dst), "l"(src))
#define CP_COMMIT() asm volatile("cp.async.commit_group;" ::: "memory")
#define CP_WAIT(N)  asm volatile("cp.async.wait_group %0;" :: "n"(N) : "memory")

#define LDSM4(R, ADDR) \
    asm volatile("ldmatrix.sync.aligned.m8n8.x4.shared.b16 {%0,%1,%2,%3}, [%4];" \
                 : "=r"((R)[0]), "=r"((R)[1]), "=r"((R)[2]), "=r"((R)[3]) \
                 : "r"(ADDR))

#define MMA_BF16(D, A, B0, B1) \
    asm volatile( \
        "mma.sync.aligned.m16n8k16.row.col.f32.bf16.bf16.f32 " \
        "{%0,%1,%2,%3}, {%4,%5,%6,%7}, {%8,%9}, {%0,%1,%2,%3};" \
        : "+f"((D)[0]), "+f"((D)[1]), "+f"((D)[2]), "+f"((D)[3]) \
        : "r"((A)[0]), "r"((A)[1]), "r"((A)[2]), "r"((A)[3]), \
          "r"(B0), "r"(B1))

__device__ __forceinline__ uint32_t pack_bf2(bf a, bf b) {
    return (uint32_t)__bfloat16_as_ushort(a) | ((uint32_t)__bfloat16_as_ushort(b) << 16);
}

// Swizzled smem layout for a 128x32 bf16 tile: row r (0..127) has four 16B
// chunks c (0..3); physical byte offset:
__device__ __forceinline__ uint32_t phys_off(int r, int c) {
    return (uint32_t)((((r) << 2) | ((c) ^ (((r) >> 1) & 3))) << 4);
}
// Conflict-free for both ldmatrix 8-row reads and cp.async warp stores.

// ---------------------------------------------------------------------------
// Static scratch (bf16 unless noted). ~450 MB.
// ---------------------------------------------------------------------------
__device__ bf g_xh [MTOT * DMODEL],  g_xl [MTOT * DMODEL];
__device__ bf g_WqTh[DINNER * DMODEL], g_WqTl[DINNER * DMODEL];
__device__ bf g_WkTh[DINNER * DMODEL], g_WkTl[DINNER * DMODEL];
__device__ bf g_WvTh[DINNER * DMODEL], g_WvTl[DINNER * DMODEL];
__device__ bf g_WoTh[DMODEL * DINNER], g_WoTl[DMODEL * DINNER];
__device__ bf g_Qh [MTOT * DINNER],  g_Ql [MTOT * DINNER];
__device__ bf g_Kh [MTOT * DINNER],  g_Kl [MTOT * DINNER];
__device__ float g_Vf [MTOT * DINNER];
__device__ bf g_VTh[MTOT * DINNER],  g_VTl[MTOT * DINNER];
__device__ bf g_Sh [BATCH * SEQ * SEQ], g_Sl[BATCH * SEQ * SEQ];
__device__ bf g_Ath[MTOT * DINNER],  g_Atl[MTOT * DINNER];
__device__ float g_den[MTOT];

// ---------------------------------------------------------------------------
// Pre/post passes
// ---------------------------------------------------------------------------
__global__ void __launch_bounds__(256)
convert_split_kernel(const float4* __restrict__ in,
                     bf* __restrict__ outh, bf* __restrict__ outl, int n4) {
    int i = blockIdx.x * 256 + threadIdx.x;
    if (i >= n4) return;
    float4 v = in[i];
    bf h0 = __float2bfloat16(v.x), h1 = __float2bfloat16(v.y);
    bf h2 = __float2bfloat16(v.z), h3 = __float2bfloat16(v.w);
    bf l0 = __float2bfloat16(v.x - __bfloat162float(h0));
    bf l1 = __float2bfloat16(v.y - __bfloat162float(h1));
    bf l2 = __float2bfloat16(v.z - __bfloat162float(h2));
    bf l3 = __float2bfloat16(v.w - __bfloat162float(h3));
    ((uint2*)outh)[i] = make_uint2(pack_bf2(h0, h1), pack_bf2(h2, h3));
    ((uint2*)outl)[i] = make_uint2(pack_bf2(l0, l1), pack_bf2(l2, l3));
}

// in: fp32 [R, C] row-major (+batch stride). out: bf16 hi/lo [C, R] (+batch stride).
__global__ void __launch_bounds__(256)
transpose_split_kernel(const float* __restrict__ in, int R, int C,
                       size_t inBatch, size_t outBatch,
                       bf* __restrict__ outh, bf* __restrict__ outl) {
    __shared__ float tile[32][33];
    int bz = blockIdx.z;
    const float* src = in + inBatch * bz;
    int c0 = blockIdx.x * 32, r0 = blockIdx.y * 32;
    int tx = threadIdx.x & 31, ty = threadIdx.x >> 5;
    #pragma unroll
    for (int i = 0; i < 4; ++i)
        tile[ty + i * 8][tx] = src[(size_t)(r0 + ty + i * 8) * C + c0 + tx];
    __syncthreads();
    #pragma unroll
    for (int i = 0; i < 4; ++i) {
        float v = tile[tx][ty + i * 8];
        bf h = __float2bfloat16(v);
        bf l = __float2bfloat16(v - __bfloat162float(h));
        size_t o = outBatch * bz + (size_t)(c0 + ty + i * 8) * R + r0 + tx;
        outh[o] = h;
        outl[o] = l;
    }
}

__global__ void __launch_bounds__(256)
rowsum_kernel(const bf* __restrict__ Sh, const bf* __restrict__ Sl,
              float* __restrict__ den) {
    int idx = blockIdx.x;                // b*SEQ + n
    int n = idx & (SEQ - 1);
    const bf* rh = Sh + (size_t)idx * SEQ;
    const bf* rl = Sl + (size_t)idx * SEQ;
    float s = 0.f;
    for (int m = threadIdx.x; m <= n; m += 256)
        s += __bfloat162float(rh[m]) + __bfloat162float(rl[m]);
    #pragma unroll
    for (int off = 16; off > 0; off >>= 1)
        s += __shfl_xor_sync(0xffffffffu, s, off);
    __shared__ float red[8];
    if ((threadIdx.x & 31) == 0) red[threadIdx.x >> 5] = s;
    __syncthreads();
    if (threadIdx.x == 0) {
        float t = 0.f;
        #pragma unroll
        for (int w = 0; w < 8; ++w) t += red[w];
        den[idx] = t + 1e-6f;
    }
}

// ---------------------------------------------------------------------------
// The HMMA bf16x3 GEMM.
//   Block tile 128x128, BK=32, 8 warps of 64x32. cp.async double buffer.
//   A: [M,K] K-major hi/lo;  B: [N,K] K-major hi/lo (i.e. B^T row-major).
//   EPI: 0 = bias+phi -> split bf16   (Q/K projections)
//        1 = bias -> fp32             (V projection, final output)
//        2 = tril mask -> split bf16  (scores; skips upper tiles)
//        3 = / den -> split bf16      (attention numerator)
// ---------------------------------------------------------------------------
static constexpr int T_AH = 0, T_AL = 8192, T_BH = 16384, T_BL = 24576;
static constexpr int STAGE = 32768;                 // 4 tiles x 8KB
static constexpr int GEMM_SMEM = 2 * STAGE;         // 64 KB

template <int EPI, bool CAUSAL>
__global__ void __launch_bounds__(256, 1)
gemm_mma(const bf* __restrict__ Ah, const bf* __restrict__ Al, int lda, size_t aB,
         const bf* __restrict__ Bh, const bf* __restrict__ Bl, int ldb, size_t bB,
         const float* __restrict__ bias, const float* __restrict__ den,
         bf* __restrict__ Oh, bf* __restrict__ Ol, float* __restrict__ Of,
         int ldo, size_t oB, int Ktot) {
    int bx = blockIdx.x, by = blockIdx.y, bz = blockIdx.z;
    if (EPI == 2 && bx > by) return;     // strictly-upper score tiles: dead

    extern __shared__ char smraw[];
    uint32_t sb = smem_to_u32(smraw);
    int tid = threadIdx.x, lane = tid & 31, wid = tid >> 5;
    const int m0 = by * 128, n0 = bx * 128;
    const int wm0 = (wid & 1) * 64, wn0 = (wid >> 1) * 32;
    Ah += aB * bz; Al += aB * bz;
    Bh += bB * bz; Bl += bB * bz;

    float acc[4][4][4];
    #pragma unroll
    for (int a = 0; a < 4; ++a)
        #pragma unroll
        for (int b = 0; b < 4; ++b)
            #pragma unroll
            for (int c = 0; c < 4; ++c) acc[a][b][c] = 0.f;

    const int kend = CAUSAL ? (by + 1) * 128 : Ktot;
    const int nch = kend >> 5;           // chunks of BK=32

    // ---- stage loader: 4 tiles x 512 16B chunks, 8 cp.async per thread ----
    auto load_stage = [&](int stg, int k0) {
        uint32_t s0 = sb + (uint32_t)stg * STAGE;
        #pragma unroll
        for (int h = 0; h < 2; ++h) {
            int id = tid + h * 256;
            int r = id >> 2, c = id & 3;
            uint32_t po = phys_off(r, c);
            const bf* ga = Ah + (size_t)(m0 + r) * lda + k0 + c * 8;
            const bf* gl = Al + (size_t)(m0 + r) * lda + k0 + c * 8;
            const bf* gb = Bh + (size_t)(n0 + r) * ldb + k0 + c * 8;
            const bf* gc = Bl + (size_t)(n0 + r) * ldb + k0 + c * 8;
            CP_ASYNC16(s0 + T_AH + po, ga);
            CP_ASYNC16(s0 + T_AL + po, gl);
            CP_ASYNC16(s0 + T_BH + po, gb);
            CP_ASYNC16(s0 + T_BL + po, gc);
        }
    };

    load_stage(0, 0);
    CP_COMMIT();

    for (int ch = 0; ch < nch; ++ch) {
        if (ch + 1 < nch) {
            load_stage((ch + 1) & 1, (ch + 1) * 32);
            CP_COMMIT();
            CP_WAIT(1);
        } else {
            CP_WAIT(0);
        }
        __syncthreads();

        uint32_t st = sb + (uint32_t)(ch & 1) * STAGE;
        #pragma unroll
        for (int s = 0; s < 2; ++s) {      // two k=16 steps per chunk
            uint32_t ah[4][4], al[4][4], bh[2][4], bl[2][4];
            #pragma unroll
            for (int mt = 0; mt < 4; ++mt) {
                int r = wm0 + mt * 16 + (lane & 15);
                int c = s * 2 + (lane >> 4);
                uint32_t off = phys_off(r, c);
                LDSM4(ah[mt], st + T_AH + off);
                LDSM4(al[mt], st + T_AL + off);
            }
            #pragma unroll
            for (int ng = 0; ng < 2; ++ng) {
                int r = wn0 + ng * 16 + (lane & 7) + ((lane >> 4) & 1) * 8;
                int c = s * 2 + ((lane >> 3) & 1);
                uint32_t off = phys_off(r, c);
                LDSM4(bh[ng], st + T_BH + off);
                LDSM4(bl[ng], st + T_BL + off);
            }
            #pragma unroll
            for (int mt = 0; mt < 4; ++mt) {
                #pragma unroll
                for (int ng = 0; ng < 2; ++ng) {
                    MMA_BF16(acc[mt][ng * 2],     ah[mt], bh[ng][0], bh[ng][1]);
                    MMA_BF16(acc[mt][ng * 2 + 1], ah[mt], bh[ng][2], bh[ng][3]);
                    MMA_BF16(acc[mt][ng * 2],     ah[mt], bl[ng][0], bl[ng][1]);
                    MMA_BF16(acc[mt][ng * 2 + 1], ah[mt], bl[ng][2], bl[ng][3]);
                    MMA_BF16(acc[mt][ng * 2],     al[mt], bh[ng][0], bh[ng][1]);
                    MMA_BF16(acc[mt][ng * 2 + 1], al[mt], bh[ng][2], bh[ng][3]);
                }
            }
        }
        __syncthreads();
    }

    // ---- epilogue ----
    #pragma unroll
    for (int mt = 0; mt < 4; ++mt) {
        #pragma unroll
        for (int hf = 0; hf < 2; ++hf) {
            int r = m0 + wm0 + mt * 16 + (lane >> 2) + hf * 8;  // row (within batch)
            float invd = 1.f;
            if (EPI == 3) invd = 1.f / den[bz * SEQ + r];
            #pragma unroll
            for (int nt = 0; nt < 4; ++nt) {
                int col = n0 + wn0 + nt * 8 + (lane & 3) * 2;
                float v0 = acc[mt][nt][hf * 2 + 0];
                float v1 = acc[mt][nt][hf * 2 + 1];
                if (EPI == 0 || EPI == 1) { v0 += __ldg(bias + col); v1 += __ldg(bias + col + 1); }
                if (EPI == 0) {
                    v0 = (v0 > 0.f) ? (v0 + 1.f) : __expf(v0);
                    v1 = (v1 > 0.f) ? (v1 + 1.f) : __expf(v1);
                }
                if (EPI == 2) {
                    v0 = (col     <= r) ? v0 : 0.f;
                    v1 = (col + 1 <= r) ? v1 : 0.f;
                }
                if (EPI == 3) { v0 *= invd; v1 *= invd; }
                if (EPI == 1) {
                    *(float2*)(Of + oB * bz + (size_t)r * ldo + col) = make_float2(v0, v1);
                } else {
                    bf h0 = __float2bfloat16(v0), h1 = __float2bfloat16(v1);
                    bf l0 = __float2bfloat16(v0 - __bfloat162float(h0));
                    bf l1 = __float2bfloat16(v1 - __bfloat162float(h1));
                    *(uint32_t*)(Oh + oB * bz + (size_t)r * ldo + col) = pack_bf2(h0, h1);
                    *(uint32_t*)(Ol + oB * bz + (size_t)r * ldo + col) = pack_bf2(l0, l1);
                }
            }
        }
    }
}

// ---------------------------------------------------------------------------
// Host launch
// ---------------------------------------------------------------------------
extern "C" void kernel_launch(void* const* d_in, const int* in_sizes, int n_in,
                              void* d_out, int out_size) {
    const float* x  = (const float*)d_in[0];
    const float* Wq = (const float*)d_in[1];
    const float* bq = (const float*)d_in[2];
    const float* Wk = (const float*)d_in[3];
    const float* bk = (const float*)d_in[4];
    const float* Wv = (const float*)d_in[5];
    const float* bv = (const float*)d_in[6];
    const float* Wo = (const float*)d_in[7];
    const float* bo = (const float*)d_in[8];
    float* out = (float*)d_out;

    #define SYM(p, s) void* p; cudaGetSymbolAddress(&p, s)
    SYM(xh, g_xh);   SYM(xl, g_xl);
    SYM(wqh, g_WqTh); SYM(wql, g_WqTl);
    SYM(wkh, g_WkTh); SYM(wkl, g_WkTl);
    SYM(wvh, g_WvTh); SYM(wvl, g_WvTl);
    SYM(woh, g_WoTh); SYM(wol, g_WoTl);
    SYM(qh, g_Qh);   SYM(ql, g_Ql);
    SYM(kh, g_Kh);   SYM(kl, g_Kl);
    SYM(vf, g_Vf);
    SYM(vth, g_VTh); SYM(vtl, g_VTl);
    SYM(sh, g_Sh);   SYM(sl, g_Sl);
    SYM(ath, g_Ath); SYM(atl, g_Atl);
    SYM(den, g_den);
    #undef SYM

    cudaFuncSetAttribute(gemm_mma<0, false>, cudaFuncAttributeMaxDynamicSharedMemorySize, GEMM_SMEM);
    cudaFuncSetAttribute(gemm_mma<1, false>, cudaFuncAttributeMaxDynamicSharedMemorySize, GEMM_SMEM);
    cudaFuncSetAttribute(gemm_mma<2, false>, cudaFuncAttributeMaxDynamicSharedMemorySize, GEMM_SMEM);
    cudaFuncSetAttribute(gemm_mma<3, true >, cudaFuncAttributeMaxDynamicSharedMemorySize, GEMM_SMEM);

    const size_t BSQ = (size_t)SEQ * SEQ;    // per-batch stride

    // ---- operand prep ----
    int n4 = MTOT * DMODEL / 4;
    convert_split_kernel<<<(n4 + 255) / 256, 256>>>((const float4*)x, (bf*)xh, (bf*)xl, n4);
    transpose_split_kernel<<<dim3(DINNER / 32, DMODEL / 32, 1), 256>>>(Wq, DMODEL, DINNER, 0, 0, (bf*)wqh, (bf*)wql);
    transpose_split_kernel<<<dim3(DINNER / 32, DMODEL / 32, 1), 256>>>(Wk, DMODEL, DINNER, 0, 0, (bf*)wkh, (bf*)wkl);
    transpose_split_kernel<<<dim3(DINNER / 32, DMODEL / 32, 1), 256>>>(Wv, DMODEL, DINNER, 0, 0, (bf*)wvh, (bf*)wvl);
    transpose_split_kernel<<<dim3(DMODEL / 32, DINNER / 32, 1), 256>>>(Wo, DINNER, DMODEL, 0, 0, (bf*)woh, (bf*)wol);

    // ---- Q/K/V projections ----
    dim3 gproj(DINNER / 128, MTOT / 128, 1);
    gemm_mma<0, false><<<gproj, 256, GEMM_SMEM>>>(
        (bf*)xh, (bf*)xl, DMODEL, 0, (bf*)wqh, (bf*)wql, DMODEL, 0,
        bq, nullptr, (bf*)qh, (bf*)ql, nullptr, DINNER, 0, DMODEL);
    gemm_mma<0, false><<<gproj, 256, GEMM_SMEM>>>(
        (bf*)xh, (bf*)xl, DMODEL, 0, (bf*)wkh, (bf*)wkl, DMODEL, 0,
        bk, nullptr, (bf*)kh, (bf*)kl, nullptr, DINNER, 0, DMODEL);
    gemm_mma<1, false><<<gproj, 256, GEMM_SMEM>>>(
        (bf*)xh, (bf*)xl, DMODEL, 0, (bf*)wvh, (bf*)wvl, DMODEL, 0,
        bv, nullptr, nullptr, nullptr, (float*)vf, DINNER, 0, DMODEL);
    transpose_split_kernel<<<dim3(DINNER / 32, SEQ / 32, BATCH), 256>>>(
        (const float*)vf, SEQ, DINNER, BSQ, BSQ, (bf*)vth, (bf*)vtl);

    // ---- scores = tril(Q K^T) ----
    gemm_mma<2, false><<<dim3(SEQ / 128, SEQ / 128, BATCH), 256, GEMM_SMEM>>>(
        (bf*)qh, (bf*)ql, DINNER, BSQ, (bf*)kh, (bf*)kl, DINNER, BSQ,
        nullptr, nullptr, (bf*)sh, (bf*)sl, nullptr, SEQ, BSQ, DINNER);

    // ---- denominator ----
    rowsum_kernel<<<MTOT, 256>>>((const bf*)sh, (const bf*)sl, (float*)den);

    // ---- numerator / den ----
    gemm_mma<3, true><<<dim3(DINNER / 128, SEQ / 128, BATCH), 256, GEMM_SMEM>>>(
        (bf*)sh, (bf*)sl, SEQ, BSQ, (bf*)vth, (bf*)vtl, SEQ, BSQ,
        nullptr, (const float*)den, (bf*)ath, (bf*)atl, nullptr, DINNER, BSQ, SEQ);

    // ---- output projection ----
    gemm_mma<1, false><<<dim3(DMODEL / 128, MTOT / 128, 1), 256, GEMM_SMEM>>>(
        (bf*)ath, (bf*)atl, DINNER, 0, (bf*)woh, (bf*)wol, DINNER, 0,
        bo, nullptr, nullptr, nullptr, out, DMODEL, 0, DINNER);
}